// round 8
// baseline (speedup 1.0000x reference)
#include <cuda_runtime.h>

#define NVOX 500000
#define CH 8
#define KT 27
#define TPB 128
#define HR 8                         // half-rows per thread
#define RPB 512                      // rows per block = (TPB/2) * HR
#define KCH 9                        // taps per smem chunk
#define HGRID ((NVOX + RPB - 1) / RPB)   // blocks per grid half (977)

// Ping-pong scratch for intermediate activations, one pair per grid.
__device__ float g_bufA0[NVOX * CH];
__device__ float g_bufB0[NVOX * CH];
__device__ float g_bufA1[NVOX * CH];
__device__ float g_bufB1[NVOX * CH];

__device__ __forceinline__ void ffma2(unsigned long long& d,
                                      unsigned long long a,
                                      unsigned long long b) {
    asm volatile("fma.rn.f32x2 %0, %1, %2, %0;" : "+l"(d) : "l"(a), "l"(b));
}

__device__ __forceinline__ unsigned long long pack2(float x) {
    unsigned long long r;
    unsigned int xb = __float_as_uint(x);
    asm("mov.b64 %0, {%1, %1};" : "=l"(r) : "r"(xb));
    return r;
}

// One sparse-conv layer over BOTH grids in one launch.
// Lane pair (2r, 2r+1) shares a row: lane h loads the row's half (cin 4h..4h+3),
// accumulates all 8 couts over its cin half; halves combined by shfl_xor at the end.
template <bool RELU, bool RES>
__global__ void __launch_bounds__(TPB, 4)
spconv_kernel(const float4* __restrict__ x0, const float4* __restrict__ x1,
              const int*    __restrict__ nbr0, const int* __restrict__ nbr1,
              const float*  __restrict__ w0, const float* __restrict__ w1,
              const float4* __restrict__ res0, const float4* __restrict__ res1,
              float4* __restrict__ out0, float4* __restrict__ out1)
{
    // Weights as f32x2 pairs: sw[k*32 + cin*4 + q] = (w[k][cin][2q], w[k][cin][2q+1])
    __shared__ __align__(16) unsigned long long sw[KT * 32];   // 6912 B
    __shared__ __align__(16) int snbr[RPB * KCH];              // 18432 B

    const int gsel = (blockIdx.x >= HGRID);
    const float4* __restrict__ x     = gsel ? x1 : x0;
    const int*    __restrict__ nbr   = gsel ? nbr1 : nbr0;
    const float*  __restrict__ w     = gsel ? w1 : w0;
    const float4* __restrict__ resid = gsel ? res1 : res0;
    float4*       __restrict__ out   = gsel ? out1 : out0;

    {
        const unsigned long long* w2 = (const unsigned long long*)w;
        for (int i = threadIdx.x; i < KT * 32; i += TPB) sw[i] = w2[i];
    }

    const int t = threadIdx.x;
    const int h = t & 1;                 // cin half (0: cin 0-3, 1: cin 4-7)
    const int pr = t >> 1;               // pair-row lane 0..63
    const int base = (blockIdx.x - (gsel ? HGRID : 0)) * RPB;
    const int rows = min(RPB, NVOX - base);

    int rl[HR], row[HR]; bool ok[HR];
#pragma unroll
    for (int s = 0; s < HR; s++) {
        rl[s] = pr + 64 * s;             // local row 0..511
        row[s] = base + rl[s];
        ok[s] = (row[s] < NVOX);
    }

    // acc[s][q] = (partial cout 2q, partial cout 2q+1) over this lane's cin half
    unsigned long long acc[HR][4];
#pragma unroll
    for (int s = 0; s < HR; s++)
#pragma unroll
        for (int q = 0; q < 4; q++) acc[s][q] = 0ull;

    const int* src = nbr + (long long)base * KT;

#pragma unroll 1
    for (int g = 0; g < 3; g++) {
        const int kbase = g * KCH;
        __syncthreads();   // covers weight staging on g==0, snbr reuse after
        {
            const int tot = rows * KCH;
            for (int i = t; i < tot; i += TPB) {
                const int r2 = i / KCH;
                const int kk = i - r2 * KCH;
                snbr[i] = src[r2 * KT + kbase + kk];
            }
        }
        __syncthreads();

#pragma unroll
        for (int u = 0; u < KCH; u++) {
            // Batch the 8 half-row gathers of this tap (MLP ~8; pair lanes share lines).
            float4 D[HR];
#pragma unroll
            for (int s = 0; s < HR; s++) {
                const int j = ok[s] ? snbr[rl[s] * KCH + u] : -1;
                D[s] = make_float4(0.f, 0.f, 0.f, 0.f);
                if (j >= 0) D[s] = __ldg(x + j * 2 + h);
            }

            const unsigned long long* wk = sw + (kbase + u) * 32 + h * 16;
#pragma unroll
            for (int ci = 0; ci < 4; ci++) {
                const ulonglong2 wA = *(const ulonglong2*)(wk + ci * 4);
                const ulonglong2 wB = *(const ulonglong2*)(wk + ci * 4 + 2);
#pragma unroll
                for (int s = 0; s < HR; s++) {
                    float f;
                    switch (ci) {
                        case 0: f = D[s].x; break;
                        case 1: f = D[s].y; break;
                        case 2: f = D[s].z; break;
                        default: f = D[s].w; break;
                    }
                    const unsigned long long p = pack2(f);
                    ffma2(acc[s][0], p, wA.x);
                    ffma2(acc[s][1], p, wA.y);
                    ffma2(acc[s][2], p, wB.x);
                    ffma2(acc[s][3], p, wB.y);
                }
            }
        }
    }

    // Epilogue: combine the two cin-half partials via shfl, act, store own half.
#pragma unroll
    for (int s = 0; s < HR; s++) {
        float v[8];
#pragma unroll
        for (int q = 0; q < 4; q++) {
            unsigned int lo, hi;
            asm("mov.b64 {%0, %1}, %2;" : "=r"(lo), "=r"(hi) : "l"(acc[s][q]));
            v[2 * q]     = __uint_as_float(lo);
            v[2 * q + 1] = __uint_as_float(hi);
        }
        // full[c] = own partial + partner partial (partner = lane ^ 1)
        float m[4];
#pragma unroll
        for (int i = 0; i < 4; i++) {
            const int c = 4 * h + i;      // couts this lane will store
            m[i] = v[c] + __shfl_xor_sync(0xffffffffu, v[c], 1);
        }
        // NOTE: shfl above exchanges v[c] where c depends on h -> both lanes
        // reference the same register slot? c differs per lane, but shfl moves
        // the *named* value each lane passes; partner passes its v[c'] with its
        // own c' = 4*h'+i which is the OTHER half -> wrong pairing. Fix: exchange
        // the partner's value for the SAME cout index: pass v[4*(1-h)+i]? Partner's
        // lane computes its own expression. Each lane passes v[4*h+i]; lane h=0
        // passes v[i], lane h=1 passes v[4+i]. Lane h=0 receives partner's v[4+i]
        // but needs partner's v[i]. So instead exchange BOTH halves explicitly below.
        (void)m;
        float full[4];
#pragma unroll
        for (int i = 0; i < 4; i++) {
            const float own  = v[4 * h + i];                 // my partial for my stored couts
            const float send = v[4 * (1 - h) + i];           // my partial for partner's couts
            const float recv = __shfl_xor_sync(0xffffffffu, send, 1);
            full[i] = own + recv;
        }
        if (ok[s]) {
            if (RES) {
                const float4 ra = resid[row[s] * 2 + h];
                full[0] += ra.x; full[1] += ra.y; full[2] += ra.z; full[3] += ra.w;
            }
            if (RELU) {
#pragma unroll
                for (int i = 0; i < 4; i++) full[i] = fmaxf(full[i], 0.f);
            }
            out[row[s] * 2 + h] = make_float4(full[0], full[1], full[2], full[3]);
        }
    }
}

extern "C" void kernel_launch(void* const* d_in, const int* in_sizes, int n_in,
                              void* d_out, int out_size) {
    (void)in_sizes; (void)n_in; (void)out_size;
    const float* feats0 = (const float*)d_in[0];
    const float* feats1 = (const float*)d_in[1];
    const float* W0     = (const float*)d_in[2];  // [3][27][8][8]
    const float* W1     = (const float*)d_in[3];
    const int*   nbr0   = (const int*)d_in[4];    // [N][27]
    const int*   nbr1   = (const int*)d_in[5];
    float* out = (float*)d_out;

    float *bufA0, *bufB0, *bufA1, *bufB1;
    cudaGetSymbolAddress((void**)&bufA0, g_bufA0);
    cudaGetSymbolAddress((void**)&bufB0, g_bufB0);
    cudaGetSymbolAddress((void**)&bufA1, g_bufA1);
    cudaGetSymbolAddress((void**)&bufB1, g_bufB1);

    const int grid = 2 * HGRID;        // both grids in one launch
    const int LW = KT * CH * CH;       // 1728 floats per layer

    spconv_kernel<true,  false><<<grid, TPB>>>(
        (const float4*)feats0, (const float4*)feats1, nbr0, nbr1,
        W0,          W1,          nullptr, nullptr,
        (float4*)bufA0, (float4*)bufA1);
    spconv_kernel<true,  false><<<grid, TPB>>>(
        (const float4*)bufA0, (const float4*)bufA1, nbr0, nbr1,
        W0 + LW,     W1 + LW,     nullptr, nullptr,
        (float4*)bufB0, (float4*)bufB1);
    spconv_kernel<false, true ><<<grid, TPB>>>(
        (const float4*)bufB0, (const float4*)bufB1, nbr0, nbr1,
        W0 + 2 * LW, W1 + 2 * LW,
        (const float4*)feats0, (const float4*)feats1,
        (float4*)out, (float4*)(out + (size_t)NVOX * CH));
}

// round 9
// speedup vs baseline: 1.0315x; 1.0315x over previous
#include <cuda_runtime.h>

#define NVOX 500000
#define CH 8
#define KT 27
#define TPB 128
#define HR 4                         // half-rows per thread
#define RPB 256                      // rows per block = (TPB/2)/1 * HR / ... = 64*4
#define KCH 9                        // taps per smem chunk
#define HGRID ((NVOX + RPB - 1) / RPB)   // blocks per grid half (1954)

// Ping-pong scratch for intermediate activations, one pair per grid.
__device__ float g_bufA0[NVOX * CH];
__device__ float g_bufB0[NVOX * CH];
__device__ float g_bufA1[NVOX * CH];
__device__ float g_bufB1[NVOX * CH];

__device__ __forceinline__ void ffma2(unsigned long long& d,
                                      unsigned long long a,
                                      unsigned long long b) {
    asm volatile("fma.rn.f32x2 %0, %1, %2, %0;" : "+l"(d) : "l"(a), "l"(b));
}

__device__ __forceinline__ unsigned long long pack2(float x) {
    unsigned long long r;
    unsigned int xb = __float_as_uint(x);
    asm("mov.b64 %0, {%1, %1};" : "=l"(r) : "r"(xb));
    return r;
}

// One sparse-conv layer over BOTH grids in one launch.
// Lane pair (2r, 2r+1) shares a row: lane h loads the row's cin half (4h..4h+3)
// with ONE LDG.128 (halves coalesce into one line), accumulates all 8 couts
// over its half; halves combined by one shfl_xor at the end.
template <bool RELU, bool RES>
__global__ void __launch_bounds__(TPB, 6)
spconv_kernel(const float4* __restrict__ x0, const float4* __restrict__ x1,
              const int*    __restrict__ nbr0, const int* __restrict__ nbr1,
              const float*  __restrict__ w0, const float* __restrict__ w1,
              const float4* __restrict__ res0, const float4* __restrict__ res1,
              float4* __restrict__ out0, float4* __restrict__ out1)
{
    // Weights as f32x2 pairs: sw[k*32 + cin*4 + q] = (w[k][cin][2q], w[k][cin][2q+1])
    __shared__ __align__(16) unsigned long long sw[KT * 32];   // 6912 B
    __shared__ __align__(16) int snbr[RPB * KCH];              // 9216 B

    const int gsel = (blockIdx.x >= HGRID);
    const float4* __restrict__ x     = gsel ? x1 : x0;
    const int*    __restrict__ nbr   = gsel ? nbr1 : nbr0;
    const float*  __restrict__ w     = gsel ? w1 : w0;
    const float4* __restrict__ resid = gsel ? res1 : res0;
    float4*       __restrict__ out   = gsel ? out1 : out0;

    {
        const unsigned long long* w2 = (const unsigned long long*)w;
        for (int i = threadIdx.x; i < KT * 32; i += TPB) sw[i] = w2[i];
    }

    const int t = threadIdx.x;
    const int h = t & 1;                 // cin half (0: cin 0-3, 1: cin 4-7)
    const int pr = t >> 1;               // pair index 0..63
    const int base = (blockIdx.x - (gsel ? HGRID : 0)) * RPB;
    const int rows = min(RPB, NVOX - base);

    int rl[HR], row[HR]; bool ok[HR];
#pragma unroll
    for (int s = 0; s < HR; s++) {
        rl[s] = pr + 64 * s;             // local row 0..255
        row[s] = base + rl[s];
        ok[s] = (row[s] < NVOX);
    }

    // acc[s][q] = (partial cout 2q, partial cout 2q+1) over this lane's cin half
    unsigned long long acc[HR][4];
#pragma unroll
    for (int s = 0; s < HR; s++)
#pragma unroll
        for (int q = 0; q < 4; q++) acc[s][q] = 0ull;

    const int* src = nbr + (long long)base * KT;

#pragma unroll 1
    for (int g = 0; g < 3; g++) {
        const int kbase = g * KCH;
        __syncthreads();   // covers weight staging on g==0, snbr reuse after
        {
            const int tot = rows * KCH;
            for (int i = t; i < tot; i += TPB) {
                const int r2 = i / KCH;
                const int kk = i - r2 * KCH;
                snbr[i] = src[r2 * KT + kbase + kk];
            }
        }
        __syncthreads();

#pragma unroll
        for (int u = 0; u < KCH; u++) {
            // Batch the HR half-row gathers of this tap (pair lanes share lines).
            float4 D[HR];
#pragma unroll
            for (int s = 0; s < HR; s++) {
                const int j = ok[s] ? snbr[rl[s] * KCH + u] : -1;
                D[s] = make_float4(0.f, 0.f, 0.f, 0.f);
                if (j >= 0) D[s] = __ldg(x + j * 2 + h);
            }

            const unsigned long long* wk = sw + (kbase + u) * 32 + h * 16;
#pragma unroll
            for (int ci = 0; ci < 4; ci++) {
                const ulonglong2 wA = *(const ulonglong2*)(wk + ci * 4);
                const ulonglong2 wB = *(const ulonglong2*)(wk + ci * 4 + 2);
#pragma unroll
                for (int s = 0; s < HR; s++) {
                    float f;
                    switch (ci) {
                        case 0: f = D[s].x; break;
                        case 1: f = D[s].y; break;
                        case 2: f = D[s].z; break;
                        default: f = D[s].w; break;
                    }
                    const unsigned long long p = pack2(f);
                    ffma2(acc[s][0], p, wA.x);
                    ffma2(acc[s][1], p, wA.y);
                    ffma2(acc[s][2], p, wB.x);
                    ffma2(acc[s][3], p, wB.y);
                }
            }
        }
    }

    // Epilogue: combine the two cin-half partials via one shfl, act, store own half.
#pragma unroll
    for (int s = 0; s < HR; s++) {
        float v[8];
#pragma unroll
        for (int q = 0; q < 4; q++) {
            unsigned int lo, hi;
            asm("mov.b64 {%0, %1}, %2;" : "=r"(lo), "=r"(hi) : "l"(acc[s][q]));
            v[2 * q]     = __uint_as_float(lo);
            v[2 * q + 1] = __uint_as_float(hi);
        }
        // Lane h stores couts 4h..4h+3. It owns partial v[4h+i]; it sends its
        // partial for the partner's couts v[4(1-h)+i] and receives the
        // partner's partial for its own couts.
        float full[4];
#pragma unroll
        for (int i = 0; i < 4; i++) {
            const float own  = v[4 * h + i];
            const float send = v[4 * (1 - h) + i];
            const float recv = __shfl_xor_sync(0xffffffffu, send, 1);
            full[i] = own + recv;
        }
        if (ok[s]) {
            if (RES) {
                const float4 ra = resid[row[s] * 2 + h];
                full[0] += ra.x; full[1] += ra.y; full[2] += ra.z; full[3] += ra.w;
            }
            if (RELU) {
#pragma unroll
                for (int i = 0; i < 4; i++) full[i] = fmaxf(full[i], 0.f);
            }
            out[row[s] * 2 + h] = make_float4(full[0], full[1], full[2], full[3]);
        }
    }
}

extern "C" void kernel_launch(void* const* d_in, const int* in_sizes, int n_in,
                              void* d_out, int out_size) {
    (void)in_sizes; (void)n_in; (void)out_size;
    const float* feats0 = (const float*)d_in[0];
    const float* feats1 = (const float*)d_in[1];
    const float* W0     = (const float*)d_in[2];  // [3][27][8][8]
    const float* W1     = (const float*)d_in[3];
    const int*   nbr0   = (const int*)d_in[4];    // [N][27]
    const int*   nbr1   = (const int*)d_in[5];
    float* out = (float*)d_out;

    float *bufA0, *bufB0, *bufA1, *bufB1;
    cudaGetSymbolAddress((void**)&bufA0, g_bufA0);
    cudaGetSymbolAddress((void**)&bufB0, g_bufB0);
    cudaGetSymbolAddress((void**)&bufA1, g_bufA1);
    cudaGetSymbolAddress((void**)&bufB1, g_bufB1);

    const int grid = 2 * HGRID;        // both grids in one launch
    const int LW = KT * CH * CH;       // 1728 floats per layer

    spconv_kernel<true,  false><<<grid, TPB>>>(
        (const float4*)feats0, (const float4*)feats1, nbr0, nbr1,
        W0,          W1,          nullptr, nullptr,
        (float4*)bufA0, (float4*)bufA1);
    spconv_kernel<true,  false><<<grid, TPB>>>(
        (const float4*)bufA0, (const float4*)bufA1, nbr0, nbr1,
        W0 + LW,     W1 + LW,     nullptr, nullptr,
        (float4*)bufB0, (float4*)bufB1);
    spconv_kernel<false, true ><<<grid, TPB>>>(
        (const float4*)bufB0, (const float4*)bufB1, nbr0, nbr1,
        W0 + 2 * LW, W1 + 2 * LW,
        (const float4*)feats0, (const float4*)feats1,
        (float4*)out, (float4*)(out + (size_t)NVOX * CH));
}

// round 10
// speedup vs baseline: 1.1696x; 1.1339x over previous
#include <cuda_runtime.h>

#define NVOX 500000
#define CH 8
#define KT 27
#define TPB 128
#define RPT 4                      // rows per thread
#define RPB (TPB * RPT)            // 512 rows per block
#define KCH 9                      // taps per smem chunk (3 chunks of 9)
#define HGRID ((NVOX + RPB - 1) / RPB)   // blocks per grid half (977)

// Ping-pong scratch for intermediate activations, one pair per grid.
__device__ float g_bufA0[NVOX * CH];
__device__ float g_bufB0[NVOX * CH];
__device__ float g_bufA1[NVOX * CH];
__device__ float g_bufB1[NVOX * CH];

__device__ __forceinline__ void ffma2(unsigned long long& d,
                                      unsigned long long a,
                                      unsigned long long b) {
    asm volatile("fma.rn.f32x2 %0, %1, %2, %0;" : "+l"(d) : "l"(a), "l"(b));
}

__device__ __forceinline__ unsigned long long pack2(float x) {
    unsigned long long r;
    unsigned int xb = __float_as_uint(x);
    asm("mov.b64 %0, {%1, %1};" : "=l"(r) : "r"(xb));
    return r;
}

// 256-bit row load (sm_100+): one LDG fetches the full 8-float row.
__device__ __forceinline__ void ldg256(const float* p, float* f) {
    asm("ld.global.nc.v8.f32 {%0,%1,%2,%3,%4,%5,%6,%7}, [%8];"
        : "=f"(f[0]), "=f"(f[1]), "=f"(f[2]), "=f"(f[3]),
          "=f"(f[4]), "=f"(f[5]), "=f"(f[6]), "=f"(f[7])
        : "l"(p));
}

__device__ __forceinline__ void stg256(float* p, const float* f) {
    asm volatile("st.global.v8.f32 [%0], {%1,%2,%3,%4,%5,%6,%7,%8};"
        :: "l"(p),
           "f"(f[0]), "f"(f[1]), "f"(f[2]), "f"(f[3]),
           "f"(f[4]), "f"(f[5]), "f"(f[6]), "f"(f[7])
        : "memory");
}

// One sparse-conv layer over BOTH grids in a single launch.
template <bool RELU, bool RES>
__global__ void __launch_bounds__(TPB, 5)
spconv_kernel(const float* __restrict__ x0, const float* __restrict__ x1,
              const int*   __restrict__ nbr0, const int* __restrict__ nbr1,
              const float* __restrict__ w0, const float* __restrict__ w1,
              const float* __restrict__ res0, const float* __restrict__ res1,
              float* __restrict__ out0, float* __restrict__ out1)
{
    // Weights as f32x2 pairs: sw[k*32 + cin*4 + p] = (w[k][cin][2p], w[k][cin][2p+1])
    __shared__ __align__(16) unsigned long long sw[KT * 32];   // 6912 B
    __shared__ __align__(16) int snbr[RPB * KCH];              // 18432 B

    const int gsel = (blockIdx.x >= HGRID);
    const float* __restrict__ x     = gsel ? x1 : x0;
    const int*   __restrict__ nbr   = gsel ? nbr1 : nbr0;
    const float* __restrict__ w     = gsel ? w1 : w0;
    const float* __restrict__ resid = gsel ? res1 : res0;
    float*       __restrict__ out   = gsel ? out1 : out0;

    {
        const unsigned long long* w2 = (const unsigned long long*)w;
        for (int i = threadIdx.x; i < KT * 32; i += TPB) sw[i] = w2[i];
    }

    const int t = threadIdx.x;
    const int base = (blockIdx.x - (gsel ? HGRID : 0)) * RPB;
    const int rows = min(RPB, NVOX - base);

    int r[RPT]; bool ok[RPT];
#pragma unroll
    for (int s = 0; s < RPT; s++) {
        r[s] = base + t + TPB * s;
        ok[s] = (r[s] < NVOX);
    }

    unsigned long long acc[RPT][4];
#pragma unroll
    for (int s = 0; s < RPT; s++)
#pragma unroll
        for (int q = 0; q < 4; q++) acc[s][q] = 0ull;

    float D0[RPT][8], D1[RPT][8];
    int j[RPT];

#define LOAD_DATA(J, D)                                          \
    {                                                            \
        _Pragma("unroll")                                        \
        for (int s = 0; s < RPT; s++) {                          \
            if (J[s] >= 0) {                                     \
                ldg256(x + (size_t)J[s] * 8, D[s]);              \
            } else {                                             \
                _Pragma("unroll")                                \
                for (int c = 0; c < 8; c++) D[s][c] = 0.f;       \
            }                                                    \
        }                                                        \
    }

#define LOAD_IDX(u, J)                                           \
    {                                                            \
        _Pragma("unroll")                                        \
        for (int s = 0; s < RPT; s++)                            \
            J[s] = ok[s] ? snbr[(t + TPB * s) * KCH + (u)] : -1; \
    }

#define FMA_TAP(k, D)                                                       \
    {                                                                       \
        const unsigned long long* wk = sw + (k) * 32;                       \
        _Pragma("unroll")                                                   \
        for (int c = 0; c < 8; c++) {                                       \
            const ulonglong2 wA = *(const ulonglong2*)(wk + c * 4);         \
            const ulonglong2 wB = *(const ulonglong2*)(wk + c * 4 + 2);     \
            _Pragma("unroll")                                               \
            for (int s = 0; s < RPT; s++) {                                 \
                const unsigned long long p = pack2(D[s][c]);                \
                ffma2(acc[s][0], p, wA.x);                                  \
                ffma2(acc[s][1], p, wA.y);                                  \
                ffma2(acc[s][2], p, wB.x);                                  \
                ffma2(acc[s][3], p, wB.y);                                  \
            }                                                               \
        }                                                                   \
    }

    const int* src = nbr + (long long)base * KT;

#pragma unroll 1
    for (int g = 0; g < 3; g++) {
        const int kbase = g * KCH;
        __syncthreads();   // also covers weight staging on g==0
        {
            const int tot = rows * KCH;
            for (int i = t; i < tot; i += TPB) {
                const int row = i / KCH;
                const int kk = i - row * KCH;
                snbr[i] = src[row * KT + kbase + kk];
            }
        }
        __syncthreads();

        // 2-deep gather pipeline over the 9 taps of this chunk.
        LOAD_IDX(0, j);
        LOAD_DATA(j, D0);
#pragma unroll
        for (int u = 0; u < KCH - 1; u++) {
            LOAD_IDX(u + 1, j);
            if (u & 1) {
                LOAD_DATA(j, D0);
                FMA_TAP(kbase + u, D1);
            } else {
                LOAD_DATA(j, D1);
                FMA_TAP(kbase + u, D0);
            }
        }
        FMA_TAP(kbase + KCH - 1, D0);   // tap 8 data sits in D0
    }

    // Epilogue
#pragma unroll
    for (int s = 0; s < RPT; s++) {
        if (!ok[s]) continue;
        float v[8];
#pragma unroll
        for (int i = 0; i < 4; i++) {
            unsigned int lo, hi;
            asm("mov.b64 {%0, %1}, %2;" : "=r"(lo), "=r"(hi) : "l"(acc[s][i]));
            v[2 * i]     = __uint_as_float(lo);
            v[2 * i + 1] = __uint_as_float(hi);
        }
        if (RES) {
            float ra[8];
            ldg256(resid + (size_t)r[s] * 8, ra);
#pragma unroll
            for (int i = 0; i < 8; i++) v[i] += ra[i];
        }
        if (RELU) {
#pragma unroll
            for (int i = 0; i < 8; i++) v[i] = fmaxf(v[i], 0.f);
        }
        stg256(out + (size_t)r[s] * 8, v);
    }
#undef LOAD_DATA
#undef LOAD_IDX
#undef FMA_TAP
}

extern "C" void kernel_launch(void* const* d_in, const int* in_sizes, int n_in,
                              void* d_out, int out_size) {
    (void)in_sizes; (void)n_in; (void)out_size;
    const float* feats0 = (const float*)d_in[0];
    const float* feats1 = (const float*)d_in[1];
    const float* W0     = (const float*)d_in[2];  // [3][27][8][8]
    const float* W1     = (const float*)d_in[3];
    const int*   nbr0   = (const int*)d_in[4];    // [N][27]
    const int*   nbr1   = (const int*)d_in[5];
    float* out = (float*)d_out;

    float *bufA0, *bufB0, *bufA1, *bufB1;
    cudaGetSymbolAddress((void**)&bufA0, g_bufA0);
    cudaGetSymbolAddress((void**)&bufB0, g_bufB0);
    cudaGetSymbolAddress((void**)&bufA1, g_bufA1);
    cudaGetSymbolAddress((void**)&bufB1, g_bufB1);

    const int grid = 2 * HGRID;        // both grids in one launch
    const int LW = KT * CH * CH;       // 1728 floats per layer

    spconv_kernel<true,  false><<<grid, TPB>>>(
        feats0, feats1, nbr0, nbr1, W0,          W1,
        nullptr, nullptr, bufA0, bufA1);
    spconv_kernel<true,  false><<<grid, TPB>>>(
        bufA0, bufA1, nbr0, nbr1, W0 + LW,     W1 + LW,
        nullptr, nullptr, bufB0, bufB1);
    spconv_kernel<false, true ><<<grid, TPB>>>(
        bufB0, bufB1, nbr0, nbr1, W0 + 2 * LW, W1 + 2 * LW,
        feats0, feats1, out, out + (size_t)NVOX * CH);
}